// round 12
// baseline (speedup 1.0000x reference)
#include <cuda_runtime.h>
#include <cuda_bf16.h>
#include <math_constants.h>
#include <stdint.h>

#define B 8
#define S 2048
#define E 1024
#define D 64
#define NROWS (B * S)
#define CHT 8      // 64-key tiles per split-k chunk

// Preconverted weights (hi/lo bf16 split), transposed: [192][E]
__device__ __nv_bfloat16 g_wt_h[3 * D * E];
__device__ __nv_bfloat16 g_wt_l[3 * D * E];
// Projected tensors (hi/lo bf16 split)
__device__ __nv_bfloat16 g_q_h[(size_t)NROWS * D], g_q_l[(size_t)NROWS * D];
__device__ __nv_bfloat16 g_k_h[(size_t)NROWS * D], g_k_l[(size_t)NROWS * D];
__device__ __nv_bfloat16 g_vt_h[(size_t)B * D * S], g_vt_l[(size_t)B * D * S]; // [b][d][s]
// Row softmax normalizer (m = 0; scores are O(1) so exp never overflows)
__device__ float g_z[NROWS];
// Per-(b,qb) completion counters for in-kernel normalization
__device__ int g_cnt[B * 32];

// ---------------------------------------------------------------------------
__device__ __forceinline__ void split2(float x, __nv_bfloat16& h, __nv_bfloat16& l) {
    h = __float2bfloat16_rn(x);
    l = __float2bfloat16_rn(x - __bfloat162float(h));
}
__device__ __forceinline__ __nv_bfloat162 mk2(__nv_bfloat16 a, __nv_bfloat16 b) {
    __nv_bfloat162 t; t.x = a; t.y = b; return t;
}
__device__ __forceinline__ uint32_t packb(__nv_bfloat16 lo, __nv_bfloat16 hi) {
    __nv_bfloat162 t; t.x = lo; t.y = hi;
    return *reinterpret_cast<uint32_t*>(&t);
}
__device__ __forceinline__ void mma16816(float* d, const uint32_t* a,
                                         uint32_t b0, uint32_t b1) {
    asm volatile(
        "mma.sync.aligned.m16n8k16.row.col.f32.bf16.bf16.f32 "
        "{%0,%1,%2,%3},{%4,%5,%6,%7},{%8,%9},{%0,%1,%2,%3};"
        : "+f"(d[0]), "+f"(d[1]), "+f"(d[2]), "+f"(d[3])
        : "r"(a[0]), "r"(a[1]), "r"(a[2]), "r"(a[3]), "r"(b0), "r"(b1));
}
__device__ __forceinline__ void ldsm4(uint32_t* r, const __nv_bfloat16* p) {
    uint32_t a = (uint32_t)__cvta_generic_to_shared(p);
    asm volatile("ldmatrix.sync.aligned.m8n8.x4.shared.b16 {%0,%1,%2,%3}, [%4];"
                 : "=r"(r[0]), "=r"(r[1]), "=r"(r[2]), "=r"(r[3]) : "r"(a));
}
__device__ __forceinline__ void cpasync16(void* smem, const void* gmem) {
    uint32_t s = (uint32_t)__cvta_generic_to_shared(smem);
    asm volatile("cp.async.ca.shared.global [%0], [%1], 16;" :: "r"(s), "l"(gmem));
}
#define CP_COMMIT() asm volatile("cp.async.commit_group;")
#define CP_WAIT(n)  asm volatile("cp.async.wait_group %0;" :: "n"(n))

// ---------------------------------------------------------------------------
// prep: blocks [0,1024) zero out (+ g_z in first 64, g_cnt in block 0);
//       blocks [1024,1072) convert W.
// ---------------------------------------------------------------------------
__global__ __launch_bounds__(256) void prep(
    float* __restrict__ out, const float* __restrict__ Wk,
    const float* __restrict__ Wq, const float* __restrict__ Wv)
{
    if (blockIdx.x < 1024) {
        reinterpret_cast<float4*>(out)[(size_t)blockIdx.x * 256 + threadIdx.x] =
            make_float4(0.f, 0.f, 0.f, 0.f);
        if (blockIdx.x < 64)
            g_z[blockIdx.x * 256 + threadIdx.x] = 0.f;
        if (blockIdx.x == 0)
            g_cnt[threadIdx.x] = 0;
    } else {
        const int wb = blockIdx.x - 1024;       // 0..47
        const int z = wb / 16, xb = wb % 16;
        const float* W = (z == 0) ? Wk : (z == 1) ? Wq : Wv;
        const int d = threadIdx.x & 63, kr = threadIdx.x >> 6;
#pragma unroll
        for (int i = 0; i < 16; i++) {
            int k = xb * 64 + i * 4 + kr;
            float v = W[(size_t)k * D + d];
            __nv_bfloat16 h, l;
            split2(v, h, l);
            g_wt_h[((size_t)z * D + d) * E + k] = h;
            g_wt_l[((size_t)z * D + d) * E + k] = l;
        }
    }
}

// ---------------------------------------------------------------------------
// Projection + upper-triangle zeroing fused (unchanged from R11). Grid (288, 2).
// ---------------------------------------------------------------------------
__global__ __launch_bounds__(256) void proj_mma(
    const float* __restrict__ seq, float* __restrict__ attn)
{
    const int nch = blockIdx.y;
    const int tid = threadIdx.x;

    if (blockIdx.x >= 256) {
        const int e = (blockIdx.x - 256) * 2 + nch;    // 0..63
        const float4 z4 = make_float4(0.f, 0.f, 0.f, 0.f);
        for (int r = e; r < NROWS; r += 64) {
            const int b = r >> 11, i = r & 2047;
            const int c0f4 = (((i >> 6) + 1) << 6) >> 2;
            float4* p = reinterpret_cast<float4*>(
                attn + (size_t)b * S * S + (size_t)i * S);
            for (int j = c0f4 + tid; j < S / 4; j += 256)
                p[j] = z4;
        }
        return;
    }

    const int row0 = blockIdx.x * 64;

    __shared__ __nv_bfloat16 Ash[2][64][40], Asl[2][64][40];
    __shared__ __nv_bfloat16 Bsh[2][96][40], Bsl[2][96][40];

    const int lane = tid & 31, wid = tid >> 5;
    const int wm = wid >> 1, wn = wid & 1;
    const int qr = lane >> 2, qc = lane & 3;
    const int lr = lane & 15, lc = (lane >> 4) << 3;

    const __nv_bfloat16* Bgh = g_wt_h + (size_t)nch * 96 * E;
    const __nv_bfloat16* Bgl = g_wt_l + (size_t)nch * 96 * E;

    const int arA = tid >> 2, acA = (tid & 3) * 8;
    const float* aptr = seq + (size_t)(row0 + arA) * E + acA;

    float acc[6][4];
#pragma unroll
    for (int c = 0; c < 6; c++)
#pragma unroll
        for (int e = 0; e < 4; e++) acc[c][e] = 0.f;

    const int NIT = E / 32;

    float4 av0 = *reinterpret_cast<const float4*>(aptr);
    float4 av1 = *reinterpret_cast<const float4*>(aptr + 4);

    {
#pragma unroll
        for (int i = 0; i < 2; i++) {
            int idx = tid + i * 256;
            if (idx < 384) {
                int r = idx >> 2, c = (idx & 3) * 8;
                cpasync16(&Bsh[0][r][c], &Bgh[(size_t)r * E + c]);
                cpasync16(&Bsl[0][r][c], &Bgl[(size_t)r * E + c]);
            }
        }
        CP_COMMIT();
    }

    for (int it = 0; it < NIT; it++) {
        const int st = it & 1;

        {
            __nv_bfloat16 h[8], l[8];
            split2(av0.x, h[0], l[0]); split2(av0.y, h[1], l[1]);
            split2(av0.z, h[2], l[2]); split2(av0.w, h[3], l[3]);
            split2(av1.x, h[4], l[4]); split2(av1.y, h[5], l[5]);
            split2(av1.z, h[6], l[6]); split2(av1.w, h[7], l[7]);
            __nv_bfloat162* ph = reinterpret_cast<__nv_bfloat162*>(&Ash[st][arA][acA]);
            __nv_bfloat162* pl = reinterpret_cast<__nv_bfloat162*>(&Asl[st][arA][acA]);
            ph[0] = mk2(h[0], h[1]); ph[1] = mk2(h[2], h[3]);
            ph[2] = mk2(h[4], h[5]); ph[3] = mk2(h[6], h[7]);
            pl[0] = mk2(l[0], l[1]); pl[1] = mk2(l[2], l[3]);
            pl[2] = mk2(l[4], l[5]); pl[3] = mk2(l[6], l[7]);
        }

        if (it + 1 < NIT) {
            const int sn = st ^ 1;
            const int k0 = (it + 1) * 32;
            av0 = *reinterpret_cast<const float4*>(aptr + k0);
            av1 = *reinterpret_cast<const float4*>(aptr + k0 + 4);
#pragma unroll
            for (int i = 0; i < 2; i++) {
                int idx = tid + i * 256;
                if (idx < 384) {
                    int r = idx >> 2, c = (idx & 3) * 8;
                    cpasync16(&Bsh[sn][r][c], &Bgh[(size_t)r * E + k0 + c]);
                    cpasync16(&Bsl[sn][r][c], &Bgl[(size_t)r * E + k0 + c]);
                }
            }
            CP_COMMIT();
            CP_WAIT(1);
        } else {
            CP_WAIT(0);
        }
        __syncthreads();

#pragma unroll
        for (int kc = 0; kc < 2; kc++) {
            int kk = kc * 16;
            uint32_t ah[4], al[4];
            ldsm4(ah, &Ash[st][wm * 16 + lr][kk + lc]);
            ldsm4(al, &Asl[st][wm * 16 + lr][kk + lc]);
#pragma unroll
            for (int nb = 0; nb < 3; nb++) {
                int n = wn * 48 + nb * 16;
                uint32_t bh[4], bl[4];
                ldsm4(bh, &Bsh[st][n + lr][kk + lc]);
                ldsm4(bl, &Bsl[st][n + lr][kk + lc]);
                mma16816(acc[nb * 2],     ah, bh[0], bh[2]);
                mma16816(acc[nb * 2],     ah, bl[0], bl[2]);
                mma16816(acc[nb * 2],     al, bh[0], bh[2]);
                mma16816(acc[nb * 2 + 1], ah, bh[1], bh[3]);
                mma16816(acc[nb * 2 + 1], ah, bl[1], bl[3]);
                mma16816(acc[nb * 2 + 1], al, bh[1], bh[3]);
            }
        }
        __syncthreads();
    }

    const int grow = row0 + wm * 16 + qr;
    const int b = grow >> 11;
    const int s1 = grow & 2047, s2 = s1 + 8;
#pragma unroll
    for (int j = 0; j < 6; j++) {
        int nb = j >> 1, sub = j & 1;
        int colf = nch * 96 + wn * 48 + nb * 16 + sub * 8 + 2 * qc;
        int z = colf >> 6, d = colf & 63;
        __nv_bfloat16 h0, h1, h2, h3, l0, l1, l2, l3;
        split2(acc[j][0], h0, l0); split2(acc[j][1], h1, l1);
        split2(acc[j][2], h2, l2); split2(acc[j][3], h3, l3);
        if (z == 2) {
            g_vt_h[((size_t)(b * D + d)) * S + s1]     = h0;
            g_vt_h[((size_t)(b * D + d + 1)) * S + s1] = h1;
            g_vt_h[((size_t)(b * D + d)) * S + s2]     = h2;
            g_vt_h[((size_t)(b * D + d + 1)) * S + s2] = h3;
            g_vt_l[((size_t)(b * D + d)) * S + s1]     = l0;
            g_vt_l[((size_t)(b * D + d + 1)) * S + s1] = l1;
            g_vt_l[((size_t)(b * D + d)) * S + s2]     = l2;
            g_vt_l[((size_t)(b * D + d + 1)) * S + s2] = l3;
        } else {
            __nv_bfloat16* oh = (z == 0) ? g_k_h : g_q_h;
            __nv_bfloat16* ol = (z == 0) ? g_k_l : g_q_l;
            *reinterpret_cast<__nv_bfloat162*>(&oh[(size_t)grow * D + d]) = mk2(h0, h1);
            *reinterpret_cast<__nv_bfloat162*>(&oh[(size_t)(grow + 8) * D + d]) = mk2(h2, h3);
            *reinterpret_cast<__nv_bfloat162*>(&ol[(size_t)grow * D + d]) = mk2(l0, l1);
            *reinterpret_cast<__nv_bfloat162*>(&ol[(size_t)(grow + 8) * D + d]) = mk2(l2, l3);
        }
    }
}

// ---------------------------------------------------------------------------
// Fused prob + out + last-chunk normalization (m = 0). Grid (80, B), 128 thr.
// ---------------------------------------------------------------------------
__global__ __launch_bounds__(128, 3) void prob_out(
    float* __restrict__ attn, float* __restrict__ out)
{
    const int b = blockIdx.y;
    const int f = 79 - blockIdx.x;          // big-work-first scheduling
    int qb, ck;
    if (f < 8)        { qb = f;                    ck = 0; }
    else if (f < 24)  { int t = f - 8;  qb = 8  + (t >> 1); ck = t & 1; }
    else if (f < 48)  { int t = f - 24; qb = 16 + t / 3;    ck = t % 3; }
    else              { int t = f - 48; qb = 24 + (t >> 2); ck = t & 3; }

    const int t0 = ck * CHT;
    const int tend = min(t0 + CHT, qb + 1);
    const int q0 = qb * 64;
    float* arow = attn + (size_t)b * S * S;

    __shared__ __nv_bfloat16 pool[8][64][72];   // 72 KB
    // K stages: pool[0],[1] (hi), pool[2],[3] (lo)
    // V stages: pool[4],[5] (hi), pool[6],[7] (lo)
    // Q staging aliases pool[0]/[1] -- consumed before K prologue.

    const int tid = threadIdx.x;
    const int lane = tid & 31, wid = tid >> 5;
    const int qr = lane >> 2, qc = lane & 3;
    const int lr = lane & 15, lc = (lane >> 4) << 3;

    const __nv_bfloat16* Qgh = g_q_h + (size_t)(b * S + q0) * D;
    const __nv_bfloat16* Qgl = g_q_l + (size_t)(b * S + q0) * D;
    const __nv_bfloat16* Kgh = g_k_h + (size_t)(b * S) * D;
    const __nv_bfloat16* Kgl = g_k_l + (size_t)(b * S) * D;
    const __nv_bfloat16* Vgh = g_vt_h + (size_t)b * D * S;
    const __nv_bfloat16* Vgl = g_vt_l + (size_t)b * D * S;

#pragma unroll
    for (int i = 0; i < 4; i++) {
        int idx = tid + i * 128;
        int r = idx >> 3, c = (idx & 7) * 8;
        *reinterpret_cast<float4*>(&pool[0][r][c]) =
            *reinterpret_cast<const float4*>(&Qgh[(size_t)r * D + c]);
        *reinterpret_cast<float4*>(&pool[1][r][c]) =
            *reinterpret_cast<const float4*>(&Qgl[(size_t)r * D + c]);
    }
    __syncthreads();

    uint32_t qah[4][4], qal[4][4];
#pragma unroll
    for (int kb = 0; kb < 4; kb++) {
        ldsm4(qah[kb], &pool[0][wid * 16 + lr][kb * 16 + lc]);
        ldsm4(qal[kb], &pool[1][wid * 16 + lr][kb * 16 + lc]);
    }
    __syncthreads();

    const int r0 = q0 + wid * 16 + qr;
    const int r1 = r0 + 8;

    float oacc[8][4];
#pragma unroll
    for (int i = 0; i < 8; i++)
#pragma unroll
        for (int j = 0; j < 4; j++) oacc[i][j] = 0.f;
    float zacc[2] = {0.f, 0.f};

#pragma unroll
    for (int i = 0; i < 4; i++) {
        int idx = tid + i * 128;
        int r = idx >> 3, c = (idx & 7) * 8;
        cpasync16(&pool[0][r][c], &Kgh[(size_t)(t0 * 64 + r) * D + c]);
        cpasync16(&pool[2][r][c], &Kgl[(size_t)(t0 * 64 + r) * D + c]);
        cpasync16(&pool[4][r][c], &Vgh[(size_t)r * S + t0 * 64 + c]);
        cpasync16(&pool[6][r][c], &Vgl[(size_t)r * S + t0 * 64 + c]);
    }
    CP_COMMIT();

    const float C = 0.18033688011112042f;   // 0.125 * log2(e)

    for (int t = t0; t < tend; t++) {
        const int st = (t - t0) & 1;
        if (t + 1 < tend) {
            const int sn = st ^ 1;
#pragma unroll
            for (int i = 0; i < 4; i++) {
                int idx = tid + i * 128;
                int r = idx >> 3, c = (idx & 7) * 8;
                cpasync16(&pool[0 + sn][r][c], &Kgh[(size_t)((t + 1) * 64 + r) * D + c]);
                cpasync16(&pool[2 + sn][r][c], &Kgl[(size_t)((t + 1) * 64 + r) * D + c]);
                cpasync16(&pool[4 + sn][r][c], &Vgh[(size_t)r * S + (t + 1) * 64 + c]);
                cpasync16(&pool[6 + sn][r][c], &Vgl[(size_t)r * S + (t + 1) * 64 + c]);
            }
            CP_COMMIT();
            CP_WAIT(1);
        } else {
            CP_WAIT(0);
        }
        __syncthreads();

#pragma unroll
        for (int h = 0; h < 2; h++) {
            float s[4][4];
#pragma unroll
            for (int a = 0; a < 4; a++)
#pragma unroll
                for (int e = 0; e < 4; e++) s[a][e] = 0.f;

#pragma unroll
            for (int kg = 0; kg < 2; kg++) {
#pragma unroll
                for (int kb = 0; kb < 4; kb++) {
                    uint32_t bh[4], bl[4];
                    ldsm4(bh, &pool[0 + st][h * 32 + kg * 16 + lr][kb * 16 + lc]);
                    ldsm4(bl, &pool[2 + st][h * 32 + kg * 16 + lr][kb * 16 + lc]);
                    mma16816(s[kg * 2],     qah[kb], bh[0], bh[2]);
                    mma16816(s[kg * 2],     qah[kb], bl[0], bl[2]);
                    mma16816(s[kg * 2],     qal[kb], bh[0], bh[2]);
                    mma16816(s[kg * 2 + 1], qah[kb], bh[1], bh[3]);
                    mma16816(s[kg * 2 + 1], qah[kb], bl[1], bl[3]);
                    mma16816(s[kg * 2 + 1], qal[kb], bh[1], bh[3]);
                }
            }

            const int colbase = t * 64 + h * 32;
#pragma unroll
            for (int nt = 0; nt < 4; nt++) {
#pragma unroll
                for (int j = 0; j < 4; j++) {
                    int col = colbase + nt * 8 + 2 * qc + (j & 1);
                    int row = (j >> 1) ? r1 : r0;
                    s[nt][j] = (col <= row) ? exp2f(s[nt][j] * C) : 0.f;
                }
                zacc[0] += s[nt][0] + s[nt][1];
                zacc[1] += s[nt][2] + s[nt][3];
            }
#pragma unroll
            for (int nt = 0; nt < 4; nt++) {
                int col = colbase + nt * 8 + 2 * qc;
                *reinterpret_cast<float2*>(&arow[(size_t)r0 * S + col]) =
                    make_float2(s[nt][0], s[nt][1]);
                *reinterpret_cast<float2*>(&arow[(size_t)r1 * S + col]) =
                    make_float2(s[nt][2], s[nt][3]);
            }
            uint32_t pah[2][4], pal[2][4];
#pragma unroll
            for (int kb = 0; kb < 2; kb++) {
                __nv_bfloat16 hh[8], ll[8];
#pragma unroll
                for (int e = 0; e < 4; e++) {
                    split2(s[kb * 2][e],     hh[e],     ll[e]);
                    split2(s[kb * 2 + 1][e], hh[4 + e], ll[4 + e]);
                }
                pah[kb][0] = packb(hh[0], hh[1]); pah[kb][1] = packb(hh[2], hh[3]);
                pah[kb][2] = packb(hh[4], hh[5]); pah[kb][3] = packb(hh[6], hh[7]);
                pal[kb][0] = packb(ll[0], ll[1]); pal[kb][1] = packb(ll[2], ll[3]);
                pal[kb][2] = packb(ll[4], ll[5]); pal[kb][3] = packb(ll[6], ll[7]);
            }
#pragma unroll
            for (int kb = 0; kb < 2; kb++) {
#pragma unroll
                for (int ntd = 0; ntd < 4; ntd++) {
                    uint32_t vh[4], vl[4];
                    ldsm4(vh, &pool[4 + st][ntd * 16 + lr][h * 32 + kb * 16 + lc]);
                    ldsm4(vl, &pool[6 + st][ntd * 16 + lr][h * 32 + kb * 16 + lc]);
                    mma16816(oacc[ntd * 2],     pah[kb], vh[0], vh[2]);
                    mma16816(oacc[ntd * 2],     pah[kb], vl[0], vl[2]);
                    mma16816(oacc[ntd * 2],     pal[kb], vh[0], vh[2]);
                    mma16816(oacc[ntd * 2 + 1], pah[kb], vh[1], vh[3]);
                    mma16816(oacc[ntd * 2 + 1], pah[kb], vl[1], vl[3]);
                    mma16816(oacc[ntd * 2 + 1], pal[kb], vh[1], vh[3]);
                }
            }
        }
        __syncthreads();
    }

#pragma unroll
    for (int rh = 0; rh < 2; rh++) {
        float z = zacc[rh];
        z += __shfl_xor_sync(0xffffffffu, z, 1);
        z += __shfl_xor_sync(0xffffffffu, z, 2);
        if ((lane & 3) == 0)
            atomicAdd(&g_z[(b << 11) + (rh ? r1 : r0)], z);
    }

#pragma unroll
    for (int no = 0; no < 8; no++) {
        int d = no * 8 + 2 * qc;
        float* p0 = &out[(size_t)(b * S + r0) * D + d];
        float* p1 = &out[(size_t)(b * S + r1) * D + d];
        atomicAdd(p0,     oacc[no][0]);
        atomicAdd(p0 + 1, oacc[no][1]);
        atomicAdd(p1,     oacc[no][2]);
        atomicAdd(p1 + 1, oacc[no][3]);
    }

    // ---- last-chunk normalization (threadfence reduction pattern) ----
    __threadfence();
    __shared__ int lastflag;
    if (tid == 0) {
        const int nck = qb / CHT + 1;
        int old = atomicAdd(&g_cnt[(b << 5) + qb], 1);
        lastflag = (old == nck - 1) ? 1 : 0;
    }
    __syncthreads();
    if (!lastflag) return;

    __shared__ float sinvZ[64];
    if (tid < 64)
        sinvZ[tid] = 1.f / g_z[(b << 11) + q0 + tid];
    __syncthreads();

    // normalize out rows [q0, q0+64)
    for (int idx = tid; idx < 64 * D; idx += 128) {
        int rr = idx >> 6;
        out[(size_t)(b * S + q0 + rr) * D + (idx & 63)] *= sinvZ[rr];
    }
    // normalize attn rows [q0, q0+64) x cols [0, (qb+1)*64)
    const int nf4 = (qb + 1) << 4;
    for (int rr = 0; rr < 64; rr++) {
        const float invZ = sinvZ[rr];
        float4* p = reinterpret_cast<float4*>(arow + (size_t)(q0 + rr) * S);
        for (int j = tid; j < nf4; j += 128) {
            float4 v = p[j];
            v.x *= invZ; v.y *= invZ; v.z *= invZ; v.w *= invZ;
            p[j] = v;
        }
    }
}

// ---------------------------------------------------------------------------
extern "C" void kernel_launch(void* const* d_in, const int* in_sizes, int n_in,
                              void* d_out, int out_size)
{
    const float* seq = (const float*)d_in[0];
    const float* Wk  = (const float*)d_in[1];
    const float* Wq  = (const float*)d_in[2];
    const float* Wv  = (const float*)d_in[3];

    float* out  = (float*)d_out;                        // [B,S,D]
    float* attn = (float*)d_out + (size_t)B * S * D;    // [B,S,S]

    prep<<<1024 + 48, 256>>>(out, Wk, Wq, Wv);
    proj_mma<<<dim3(288, 2), 256>>>(seq, attn);
    prob_out<<<dim3(80, B), 128>>>(attn, out);
}

// round 13
// speedup vs baseline: 1.3509x; 1.3509x over previous
#include <cuda_runtime.h>
#include <cuda_bf16.h>
#include <math_constants.h>
#include <stdint.h>

#define B 8
#define S 2048
#define E 1024
#define D 64
#define NROWS (B * S)
#define CHT 8      // 64-key tiles per split-k chunk

// Preconverted weights (hi/lo bf16 split), transposed: [192][E]
__device__ __nv_bfloat16 g_wt_h[3 * D * E];
__device__ __nv_bfloat16 g_wt_l[3 * D * E];
// Projected tensors (hi/lo bf16 split)
__device__ __nv_bfloat16 g_q_h[(size_t)NROWS * D], g_q_l[(size_t)NROWS * D];
__device__ __nv_bfloat16 g_k_h[(size_t)NROWS * D], g_k_l[(size_t)NROWS * D];
__device__ __nv_bfloat16 g_vt_h[(size_t)B * D * S], g_vt_l[(size_t)B * D * S]; // [b][d][s]
// Row softmax normalizer (m = 0; scores are O(1) so exp never overflows)
__device__ float g_z[NROWS];

// ---------------------------------------------------------------------------
__device__ __forceinline__ void split2(float x, __nv_bfloat16& h, __nv_bfloat16& l) {
    h = __float2bfloat16_rn(x);
    l = __float2bfloat16_rn(x - __bfloat162float(h));
}
__device__ __forceinline__ __nv_bfloat162 mk2(__nv_bfloat16 a, __nv_bfloat16 b) {
    __nv_bfloat162 t; t.x = a; t.y = b; return t;
}
__device__ __forceinline__ uint32_t packb(__nv_bfloat16 lo, __nv_bfloat16 hi) {
    __nv_bfloat162 t; t.x = lo; t.y = hi;
    return *reinterpret_cast<uint32_t*>(&t);
}
__device__ __forceinline__ void mma16816(float* d, const uint32_t* a,
                                         uint32_t b0, uint32_t b1) {
    asm volatile(
        "mma.sync.aligned.m16n8k16.row.col.f32.bf16.bf16.f32 "
        "{%0,%1,%2,%3},{%4,%5,%6,%7},{%8,%9},{%0,%1,%2,%3};"
        : "+f"(d[0]), "+f"(d[1]), "+f"(d[2]), "+f"(d[3])
        : "r"(a[0]), "r"(a[1]), "r"(a[2]), "r"(a[3]), "r"(b0), "r"(b1));
}
__device__ __forceinline__ void ldsm4(uint32_t* r, const __nv_bfloat16* p) {
    uint32_t a = (uint32_t)__cvta_generic_to_shared(p);
    asm volatile("ldmatrix.sync.aligned.m8n8.x4.shared.b16 {%0,%1,%2,%3}, [%4];"
                 : "=r"(r[0]), "=r"(r[1]), "=r"(r[2]), "=r"(r[3]) : "r"(a));
}
__device__ __forceinline__ void cpasync16(void* smem, const void* gmem) {
    uint32_t s = (uint32_t)__cvta_generic_to_shared(smem);
    asm volatile("cp.async.ca.shared.global [%0], [%1], 16;" :: "r"(s), "l"(gmem));
}
#define CP_COMMIT() asm volatile("cp.async.commit_group;")
#define CP_WAIT(n)  asm volatile("cp.async.wait_group %0;" :: "n"(n))

// ---------------------------------------------------------------------------
// conv_w: W[k][d] -> Wt[z][d][k] hi/lo via smem transpose, coalesced both ways.
// Grid (16, 3): one 64(k) x 64(d) tile per block.
// ---------------------------------------------------------------------------
__global__ __launch_bounds__(256) void conv_w(
    const float* __restrict__ Wk, const float* __restrict__ Wq,
    const float* __restrict__ Wv)
{
    const int z = blockIdx.y, kt = blockIdx.x;
    const float* W = (z == 0) ? Wk : (z == 1) ? Wq : Wv;
    const int tid = threadIdx.x;

    __shared__ float T[64][65];   // [d][k], padded

    // Load 64 k-rows x 64 d, transposing into T: 1024 float4, 4 per thread.
#pragma unroll
    for (int i = 0; i < 4; i++) {
        int idx = tid + i * 256;
        int k = idx >> 4, d4 = (idx & 15) * 4;
        float4 v = *reinterpret_cast<const float4*>(
            &W[(size_t)(kt * 64 + k) * D + d4]);
        T[d4 + 0][k] = v.x; T[d4 + 1][k] = v.y;
        T[d4 + 2][k] = v.z; T[d4 + 3][k] = v.w;
    }
    __syncthreads();

    // Each thread: one d row, 16 contiguous k -> 32B contiguous stores.
    const int d = tid >> 2, kg = (tid & 3) * 16;
    __align__(16) __nv_bfloat16 hbuf[16], lbuf[16];
#pragma unroll
    for (int j = 0; j < 16; j++) split2(T[d][kg + j], hbuf[j], lbuf[j]);
    const size_t base = ((size_t)z * D + d) * E + kt * 64 + kg;
    *reinterpret_cast<float4*>(&g_wt_h[base])     = *reinterpret_cast<float4*>(&hbuf[0]);
    *reinterpret_cast<float4*>(&g_wt_h[base + 8]) = *reinterpret_cast<float4*>(&hbuf[8]);
    *reinterpret_cast<float4*>(&g_wt_l[base])     = *reinterpret_cast<float4*>(&lbuf[0]);
    *reinterpret_cast<float4*>(&g_wt_l[base + 8]) = *reinterpret_cast<float4*>(&lbuf[8]);
}

// ---------------------------------------------------------------------------
// Projection + zero streaming fused. Grid (288, 2):
//   x <  256: GEMM (64 rows x 96 cols of 192).
//   x >= 256: zero attn strictly-upper region + out + g_z (overlaps the GEMM).
// ---------------------------------------------------------------------------
__global__ __launch_bounds__(256) void proj_mma(
    const float* __restrict__ seq, float* __restrict__ attn,
    float* __restrict__ out)
{
    const int nch = blockIdx.y;
    const int tid = threadIdx.x;

    if (blockIdx.x >= 256) {
        const int e = (blockIdx.x - 256) * 2 + nch;    // 0..63
        const float4 z4 = make_float4(0.f, 0.f, 0.f, 0.f);
        // zero out: 262144 float4 over 64 blocks
        {
            float4* po = reinterpret_cast<float4*>(out);
            for (int j = e * 4096 + tid; j < (e + 1) * 4096; j += 256)
                po[j] = z4;
        }
        // zero g_z: 16384 floats, one per thread
        g_z[e * 256 + tid] = 0.f;
        // zero attn strictly-upper region, rows round-robin
        for (int r = e; r < NROWS; r += 64) {
            const int b = r >> 11, i = r & 2047;
            const int c0f4 = (((i >> 6) + 1) << 6) >> 2;
            float4* p = reinterpret_cast<float4*>(
                attn + (size_t)b * S * S + (size_t)i * S);
            for (int j = c0f4 + tid; j < S / 4; j += 256)
                p[j] = z4;
        }
        return;
    }

    const int row0 = blockIdx.x * 64;

    __shared__ __nv_bfloat16 Ash[2][64][40], Asl[2][64][40];
    __shared__ __nv_bfloat16 Bsh[2][96][40], Bsl[2][96][40];

    const int lane = tid & 31, wid = tid >> 5;
    const int wm = wid >> 1, wn = wid & 1;
    const int qr = lane >> 2, qc = lane & 3;
    const int lr = lane & 15, lc = (lane >> 4) << 3;

    const __nv_bfloat16* Bgh = g_wt_h + (size_t)nch * 96 * E;
    const __nv_bfloat16* Bgl = g_wt_l + (size_t)nch * 96 * E;

    const int arA = tid >> 2, acA = (tid & 3) * 8;
    const float* aptr = seq + (size_t)(row0 + arA) * E + acA;

    float acc[6][4];
#pragma unroll
    for (int c = 0; c < 6; c++)
#pragma unroll
        for (int e = 0; e < 4; e++) acc[c][e] = 0.f;

    const int NIT = E / 32;

    float4 av0 = *reinterpret_cast<const float4*>(aptr);
    float4 av1 = *reinterpret_cast<const float4*>(aptr + 4);

    {
#pragma unroll
        for (int i = 0; i < 2; i++) {
            int idx = tid + i * 256;
            if (idx < 384) {
                int r = idx >> 2, c = (idx & 3) * 8;
                cpasync16(&Bsh[0][r][c], &Bgh[(size_t)r * E + c]);
                cpasync16(&Bsl[0][r][c], &Bgl[(size_t)r * E + c]);
            }
        }
        CP_COMMIT();
    }

    for (int it = 0; it < NIT; it++) {
        const int st = it & 1;

        {
            __nv_bfloat16 h[8], l[8];
            split2(av0.x, h[0], l[0]); split2(av0.y, h[1], l[1]);
            split2(av0.z, h[2], l[2]); split2(av0.w, h[3], l[3]);
            split2(av1.x, h[4], l[4]); split2(av1.y, h[5], l[5]);
            split2(av1.z, h[6], l[6]); split2(av1.w, h[7], l[7]);
            __nv_bfloat162* ph = reinterpret_cast<__nv_bfloat162*>(&Ash[st][arA][acA]);
            __nv_bfloat162* pl = reinterpret_cast<__nv_bfloat162*>(&Asl[st][arA][acA]);
            ph[0] = mk2(h[0], h[1]); ph[1] = mk2(h[2], h[3]);
            ph[2] = mk2(h[4], h[5]); ph[3] = mk2(h[6], h[7]);
            pl[0] = mk2(l[0], l[1]); pl[1] = mk2(l[2], l[3]);
            pl[2] = mk2(l[4], l[5]); pl[3] = mk2(l[6], l[7]);
        }

        if (it + 1 < NIT) {
            const int sn = st ^ 1;
            const int k0 = (it + 1) * 32;
            av0 = *reinterpret_cast<const float4*>(aptr + k0);
            av1 = *reinterpret_cast<const float4*>(aptr + k0 + 4);
#pragma unroll
            for (int i = 0; i < 2; i++) {
                int idx = tid + i * 256;
                if (idx < 384) {
                    int r = idx >> 2, c = (idx & 3) * 8;
                    cpasync16(&Bsh[sn][r][c], &Bgh[(size_t)r * E + k0 + c]);
                    cpasync16(&Bsl[sn][r][c], &Bgl[(size_t)r * E + k0 + c]);
                }
            }
            CP_COMMIT();
            CP_WAIT(1);
        } else {
            CP_WAIT(0);
        }
        __syncthreads();

#pragma unroll
        for (int kc = 0; kc < 2; kc++) {
            int kk = kc * 16;
            uint32_t ah[4], al[4];
            ldsm4(ah, &Ash[st][wm * 16 + lr][kk + lc]);
            ldsm4(al, &Asl[st][wm * 16 + lr][kk + lc]);
#pragma unroll
            for (int nb = 0; nb < 3; nb++) {
                int n = wn * 48 + nb * 16;
                uint32_t bh[4], bl[4];
                ldsm4(bh, &Bsh[st][n + lr][kk + lc]);
                ldsm4(bl, &Bsl[st][n + lr][kk + lc]);
                mma16816(acc[nb * 2],     ah, bh[0], bh[2]);
                mma16816(acc[nb * 2],     ah, bl[0], bl[2]);
                mma16816(acc[nb * 2],     al, bh[0], bh[2]);
                mma16816(acc[nb * 2 + 1], ah, bh[1], bh[3]);
                mma16816(acc[nb * 2 + 1], ah, bl[1], bl[3]);
                mma16816(acc[nb * 2 + 1], al, bh[1], bh[3]);
            }
        }
        __syncthreads();
    }

    const int grow = row0 + wm * 16 + qr;
    const int b = grow >> 11;
    const int s1 = grow & 2047, s2 = s1 + 8;
#pragma unroll
    for (int j = 0; j < 6; j++) {
        int nb = j >> 1, sub = j & 1;
        int colf = nch * 96 + wn * 48 + nb * 16 + sub * 8 + 2 * qc;
        int z = colf >> 6, d = colf & 63;
        __nv_bfloat16 h0, h1, h2, h3, l0, l1, l2, l3;
        split2(acc[j][0], h0, l0); split2(acc[j][1], h1, l1);
        split2(acc[j][2], h2, l2); split2(acc[j][3], h3, l3);
        if (z == 2) {
            g_vt_h[((size_t)(b * D + d)) * S + s1]     = h0;
            g_vt_h[((size_t)(b * D + d + 1)) * S + s1] = h1;
            g_vt_h[((size_t)(b * D + d)) * S + s2]     = h2;
            g_vt_h[((size_t)(b * D + d + 1)) * S + s2] = h3;
            g_vt_l[((size_t)(b * D + d)) * S + s1]     = l0;
            g_vt_l[((size_t)(b * D + d + 1)) * S + s1] = l1;
            g_vt_l[((size_t)(b * D + d)) * S + s2]     = l2;
            g_vt_l[((size_t)(b * D + d + 1)) * S + s2] = l3;
        } else {
            __nv_bfloat16* oh = (z == 0) ? g_k_h : g_q_h;
            __nv_bfloat16* ol = (z == 0) ? g_k_l : g_q_l;
            *reinterpret_cast<__nv_bfloat162*>(&oh[(size_t)grow * D + d]) = mk2(h0, h1);
            *reinterpret_cast<__nv_bfloat162*>(&oh[(size_t)(grow + 8) * D + d]) = mk2(h2, h3);
            *reinterpret_cast<__nv_bfloat162*>(&ol[(size_t)grow * D + d]) = mk2(l0, l1);
            *reinterpret_cast<__nv_bfloat162*>(&ol[(size_t)(grow + 8) * D + d]) = mk2(l2, l3);
        }
    }
}

// ---------------------------------------------------------------------------
// Fused prob + out (m = 0). Grid (80, B), 128 threads. Big-work-first.
// ---------------------------------------------------------------------------
__global__ __launch_bounds__(128, 3) void prob_out(
    float* __restrict__ attn, float* __restrict__ out)
{
    const int b = blockIdx.y;
    const int f = 79 - blockIdx.x;
    int qb, ck;
    if (f < 8)        { qb = f;                    ck = 0; }
    else if (f < 24)  { int t = f - 8;  qb = 8  + (t >> 1); ck = t & 1; }
    else if (f < 48)  { int t = f - 24; qb = 16 + t / 3;    ck = t % 3; }
    else              { int t = f - 48; qb = 24 + (t >> 2); ck = t & 3; }

    const int t0 = ck * CHT;
    const int tend = min(t0 + CHT, qb + 1);
    const int q0 = qb * 64;
    float* arow = attn + (size_t)b * S * S;

    __shared__ __nv_bfloat16 pool[8][64][72];   // 72 KB

    const int tid = threadIdx.x;
    const int lane = tid & 31, wid = tid >> 5;
    const int qr = lane >> 2, qc = lane & 3;
    const int lr = lane & 15, lc = (lane >> 4) << 3;

    const __nv_bfloat16* Qgh = g_q_h + (size_t)(b * S + q0) * D;
    const __nv_bfloat16* Qgl = g_q_l + (size_t)(b * S + q0) * D;
    const __nv_bfloat16* Kgh = g_k_h + (size_t)(b * S) * D;
    const __nv_bfloat16* Kgl = g_k_l + (size_t)(b * S) * D;
    const __nv_bfloat16* Vgh = g_vt_h + (size_t)b * D * S;
    const __nv_bfloat16* Vgl = g_vt_l + (size_t)b * D * S;

#pragma unroll
    for (int i = 0; i < 4; i++) {
        int idx = tid + i * 128;
        int r = idx >> 3, c = (idx & 7) * 8;
        *reinterpret_cast<float4*>(&pool[0][r][c]) =
            *reinterpret_cast<const float4*>(&Qgh[(size_t)r * D + c]);
        *reinterpret_cast<float4*>(&pool[1][r][c]) =
            *reinterpret_cast<const float4*>(&Qgl[(size_t)r * D + c]);
    }
    __syncthreads();

    uint32_t qah[4][4], qal[4][4];
#pragma unroll
    for (int kb = 0; kb < 4; kb++) {
        ldsm4(qah[kb], &pool[0][wid * 16 + lr][kb * 16 + lc]);
        ldsm4(qal[kb], &pool[1][wid * 16 + lr][kb * 16 + lc]);
    }
    __syncthreads();

    const int r0 = q0 + wid * 16 + qr;
    const int r1 = r0 + 8;

    float oacc[8][4];
#pragma unroll
    for (int i = 0; i < 8; i++)
#pragma unroll
        for (int j = 0; j < 4; j++) oacc[i][j] = 0.f;
    float zacc[2] = {0.f, 0.f};

#pragma unroll
    for (int i = 0; i < 4; i++) {
        int idx = tid + i * 128;
        int r = idx >> 3, c = (idx & 7) * 8;
        cpasync16(&pool[0][r][c], &Kgh[(size_t)(t0 * 64 + r) * D + c]);
        cpasync16(&pool[2][r][c], &Kgl[(size_t)(t0 * 64 + r) * D + c]);
        cpasync16(&pool[4][r][c], &Vgh[(size_t)r * S + t0 * 64 + c]);
        cpasync16(&pool[6][r][c], &Vgl[(size_t)r * S + t0 * 64 + c]);
    }
    CP_COMMIT();

    const float C = 0.18033688011112042f;   // 0.125 * log2(e)

    for (int t = t0; t < tend; t++) {
        const int st = (t - t0) & 1;
        if (t + 1 < tend) {
            const int sn = st ^ 1;
#pragma unroll
            for (int i = 0; i < 4; i++) {
                int idx = tid + i * 128;
                int r = idx >> 3, c = (idx & 7) * 8;
                cpasync16(&pool[0 + sn][r][c], &Kgh[(size_t)((t + 1) * 64 + r) * D + c]);
                cpasync16(&pool[2 + sn][r][c], &Kgl[(size_t)((t + 1) * 64 + r) * D + c]);
                cpasync16(&pool[4 + sn][r][c], &Vgh[(size_t)r * S + (t + 1) * 64 + c]);
                cpasync16(&pool[6 + sn][r][c], &Vgl[(size_t)r * S + (t + 1) * 64 + c]);
            }
            CP_COMMIT();
            CP_WAIT(1);
        } else {
            CP_WAIT(0);
        }
        __syncthreads();

#pragma unroll
        for (int h = 0; h < 2; h++) {
            float s[4][4];
#pragma unroll
            for (int a = 0; a < 4; a++)
#pragma unroll
                for (int e = 0; e < 4; e++) s[a][e] = 0.f;

#pragma unroll
            for (int kg = 0; kg < 2; kg++) {
#pragma unroll
                for (int kb = 0; kb < 4; kb++) {
                    uint32_t bh[4], bl[4];
                    ldsm4(bh, &pool[0 + st][h * 32 + kg * 16 + lr][kb * 16 + lc]);
                    ldsm4(bl, &pool[2 + st][h * 32 + kg * 16 + lr][kb * 16 + lc]);
                    mma16816(s[kg * 2],     qah[kb], bh[0], bh[2]);
                    mma16816(s[kg * 2],     qah[kb], bl[0], bl[2]);
                    mma16816(s[kg * 2],     qal[kb], bh[0], bh[2]);
                    mma16816(s[kg * 2 + 1], qah[kb], bh[1], bh[3]);
                    mma16816(s[kg * 2 + 1], qah[kb], bl[1], bl[3]);
                    mma16816(s[kg * 2 + 1], qal[kb], bh[1], bh[3]);
                }
            }

            const int colbase = t * 64 + h * 32;
#pragma unroll
            for (int nt = 0; nt < 4; nt++) {
#pragma unroll
                for (int j = 0; j < 4; j++) {
                    int col = colbase + nt * 8 + 2 * qc + (j & 1);
                    int row = (j >> 1) ? r1 : r0;
                    s[nt][j] = (col <= row) ? exp2f(s[nt][j] * C) : 0.f;
                }
                zacc[0] += s[nt][0] + s[nt][1];
                zacc[1] += s[nt][2] + s[nt][3];
            }
#pragma unroll
            for (int nt = 0; nt < 4; nt++) {
                int col = colbase + nt * 8 + 2 * qc;
                *reinterpret_cast<float2*>(&arow[(size_t)r0 * S + col]) =
                    make_float2(s[nt][0], s[nt][1]);
                *reinterpret_cast<float2*>(&arow[(size_t)r1 * S + col]) =
                    make_float2(s[nt][2], s[nt][3]);
            }
            uint32_t pah[2][4], pal[2][4];
#pragma unroll
            for (int kb = 0; kb < 2; kb++) {
                __nv_bfloat16 hh[8], ll[8];
#pragma unroll
                for (int e = 0; e < 4; e++) {
                    split2(s[kb * 2][e],     hh[e],     ll[e]);
                    split2(s[kb * 2 + 1][e], hh[4 + e], ll[4 + e]);
                }
                pah[kb][0] = packb(hh[0], hh[1]); pah[kb][1] = packb(hh[2], hh[3]);
                pah[kb][2] = packb(hh[4], hh[5]); pah[kb][3] = packb(hh[6], hh[7]);
                pal[kb][0] = packb(ll[0], ll[1]); pal[kb][1] = packb(ll[2], ll[3]);
                pal[kb][2] = packb(ll[4], ll[5]); pal[kb][3] = packb(ll[6], ll[7]);
            }
#pragma unroll
            for (int kb = 0; kb < 2; kb++) {
#pragma unroll
                for (int ntd = 0; ntd < 4; ntd++) {
                    uint32_t vh[4], vl[4];
                    ldsm4(vh, &pool[4 + st][ntd * 16 + lr][h * 32 + kb * 16 + lc]);
                    ldsm4(vl, &pool[6 + st][ntd * 16 + lr][h * 32 + kb * 16 + lc]);
                    mma16816(oacc[ntd * 2],     pah[kb], vh[0], vh[2]);
                    mma16816(oacc[ntd * 2],     pah[kb], vl[0], vl[2]);
                    mma16816(oacc[ntd * 2],     pal[kb], vh[0], vh[2]);
                    mma16816(oacc[ntd * 2 + 1], pah[kb], vh[1], vh[3]);
                    mma16816(oacc[ntd * 2 + 1], pah[kb], vl[1], vl[3]);
                    mma16816(oacc[ntd * 2 + 1], pal[kb], vh[1], vh[3]);
                }
            }
        }
        __syncthreads();
    }

#pragma unroll
    for (int rh = 0; rh < 2; rh++) {
        float z = zacc[rh];
        z += __shfl_xor_sync(0xffffffffu, z, 1);
        z += __shfl_xor_sync(0xffffffffu, z, 2);
        if ((lane & 3) == 0)
            atomicAdd(&g_z[(b << 11) + (rh ? r1 : r0)], z);
    }

#pragma unroll
    for (int no = 0; no < 8; no++) {
        int d = no * 8 + 2 * qc;
        float* p0 = &out[(size_t)(b * S + r0) * D + d];
        float* p1 = &out[(size_t)(b * S + r1) * D + d];
        atomicAdd(p0,     oacc[no][0]);
        atomicAdd(p0 + 1, oacc[no][1]);
        atomicAdd(p1,     oacc[no][2]);
        atomicAdd(p1 + 1, oacc[no][3]);
    }
}

// ---------------------------------------------------------------------------
// Finalize: scale the prob_out-written region (cols < (qb+1)*64) by 1/Z;
// upper tiles already zeroed in proj_mma. Also normalize the out row.
// ---------------------------------------------------------------------------
__global__ __launch_bounds__(256) void finalize_all(
    float* __restrict__ attn, float* __restrict__ out)
{
    const int row = blockIdx.x;
    const int b = row >> 11, i = row & 2047;
    const int qb = i >> 6;
    float4* p = reinterpret_cast<float4*>(attn + (size_t)b * S * S + (size_t)i * S);
    const float invZ = 1.f / g_z[row];

    const int nf4 = (qb + 1) << 4;
    for (int j = threadIdx.x; j < nf4; j += 256) {
        float4 v = p[j];
        v.x *= invZ; v.y *= invZ; v.z *= invZ; v.w *= invZ;
        p[j] = v;
    }

    if (threadIdx.x < 64)
        out[(size_t)row * D + threadIdx.x] *= invZ;
}

// ---------------------------------------------------------------------------
extern "C" void kernel_launch(void* const* d_in, const int* in_sizes, int n_in,
                              void* d_out, int out_size)
{
    const float* seq = (const float*)d_in[0];
    const float* Wk  = (const float*)d_in[1];
    const float* Wq  = (const float*)d_in[2];
    const float* Wv  = (const float*)d_in[3];

    float* out  = (float*)d_out;                        // [B,S,D]
    float* attn = (float*)d_out + (size_t)B * S * D;    // [B,S,S]

    conv_w<<<dim3(16, 3), 256>>>(Wk, Wq, Wv);
    proj_mma<<<dim3(288, 2), 256>>>(seq, attn, out);
    prob_out<<<dim3(80, B), 128>>>(attn, out);
    finalize_all<<<NROWS, 256>>>(attn, out);
}